// round 6
// baseline (speedup 1.0000x reference)
#include <cuda_runtime.h>

// out = feat @ Wv + bv
//
// The reference's softmax over axis=-2 (j) followed by einsum('ijk,ik->ik')
// (a sum over j) makes the attention-weight branch sum to exactly 1 per
// (i,k), so out[i,k] == v[i,k] == (feat @ Wv + bv)[i,k].
//
// feat: [N=1024, C=256] f32   (d_in[0])
// Wv:   [C, C]          f32   (d_in[9])
// bv:   [C]             f32   (d_in[10])
// out:  [N, C]          f32

namespace {

constexpr int Ndim = 1024;
constexpr int Cdim = 256;
constexpr int TM = 64;    // rows per block
constexpr int TN = 32;    // cols per block
constexpr int KC = 64;    // k-chunk (4 chunks, double-buffered smem)
constexpr int CHUNKS = Cdim / KC;
constexpr int SAT_STRIDE = TM + 4;  // 68 floats: 16B-aligned rows, bank-staggered

// 256 threads = 8 warps = 2 warps/SMSP, 4x2 micro-tile (8 FFMA : 2 LDS/iter).
// Key change vs R5: the shared-memory fragments are software-pipelined 2
// k-iterations ahead in registers, so the 29-cycle LDS latency is never on
// the critical path — the inner loop issues LDS for k+2 and immediately
// FFMAs on k's already-resident registers. Grid = 128 blocks, one wave.

__global__ __launch_bounds__(256, 1)
void vgemm_bias_kernel(const float* __restrict__ A,    // [N, C] feat
                       const float* __restrict__ B,    // [C, C] Wv
                       const float* __restrict__ bias, // [C]
                       float* __restrict__ O)          // [N, C]
{
    __shared__ float sAT[2][KC][SAT_STRIDE];  // A tile, k-major (transposed)
    __shared__ float sB [2][KC][TN];          // B tile, k-major

    const int tid  = threadIdx.x;   // 0..255
    const int lane = tid & 31;
    const int warp = tid >> 5;      // 0..7
    const int tn   = tid & 15;      // col group (x2)
    const int tm   = tid >> 4;      // row group (x4)

    const int row0 = blockIdx.y * TM;
    const int col0 = blockIdx.x * TN;

    // ---- tile loaders (global -> smem) ----
    auto load_tiles = [&](int kk, int buf) {
        // A: transpose during load. Unit u covers rows m0..m0+3, 32 k's.
        #pragma unroll
        for (int i = 0; i < 4; i++) {
            const int u  = warp * 4 + i;           // 0..31
            const int m0 = (u & 15) * 4;           // 0,4,...,60
            const int k  = ((u >> 4) << 5) + lane; // 0..63
            const float* gp = &A[(row0 + m0) * Cdim + kk + k];
            float4 v;
            v.x = gp[0 * Cdim];
            v.y = gp[1 * Cdim];
            v.z = gp[2 * Cdim];
            v.w = gp[3 * Cdim];
            *reinterpret_cast<float4*>(&sAT[buf][k][m0]) = v;
        }
        // B tile: 64 k x 32 n = 512 float4; 2 per thread, fully coalesced.
        #pragma unroll
        for (int i = 0; i < 2; i++) {
            const int idx = i * 256 + tid;   // 0..511
            const int r   = idx >> 3;        // 8 float4 per row
            const int c4  = (idx & 7) * 4;
            *reinterpret_cast<float4*>(&sB[buf][r][c4]) =
                *reinterpret_cast<const float4*>(&B[(kk + r) * Cdim + col0 + c4]);
        }
    };

    float acc[4][2];
    #pragma unroll
    for (int r = 0; r < 4; r++) {
        acc[r][0] = 0.f;
        acc[r][1] = 0.f;
    }

    load_tiles(0, 0);
    __syncthreads();

    for (int chunk = 0; chunk < CHUNKS; chunk++) {   // rolled: keeps I$ small
        const int buf = chunk & 1;

        // kick off next chunk's global loads first (longest latency)
        if (chunk + 1 < CHUNKS)
            load_tiles((chunk + 1) * KC, buf ^ 1);

        // ---- register pipeline: preload k = 0, 1 ----
        float4 pa[2];
        float2 pb[2];
        pa[0] = *reinterpret_cast<const float4*>(&sAT[buf][0][tm * 4]);
        pb[0] = *reinterpret_cast<const float2*>(&sB [buf][0][tn * 2]);
        pa[1] = *reinterpret_cast<const float4*>(&sAT[buf][1][tm * 4]);
        pb[1] = *reinterpret_cast<const float2*>(&sB [buf][1][tn * 2]);

        #pragma unroll
        for (int k = 0; k < KC; k++) {
            const float4 a = pa[k & 1];
            const float2 b = pb[k & 1];

            // prefetch k+2 (clamped at the tail; redundant loads are harmless)
            const int kn = (k + 2 < KC) ? (k + 2) : (KC - 1);
            pa[k & 1] = *reinterpret_cast<const float4*>(&sAT[buf][kn][tm * 4]);
            pb[k & 1] = *reinterpret_cast<const float2*>(&sB [buf][kn][tn * 2]);

            acc[0][0] = fmaf(a.x, b.x, acc[0][0]);
            acc[0][1] = fmaf(a.x, b.y, acc[0][1]);
            acc[1][0] = fmaf(a.y, b.x, acc[1][0]);
            acc[1][1] = fmaf(a.y, b.y, acc[1][1]);
            acc[2][0] = fmaf(a.z, b.x, acc[2][0]);
            acc[2][1] = fmaf(a.z, b.y, acc[2][1]);
            acc[3][0] = fmaf(a.w, b.x, acc[3][0]);
            acc[3][1] = fmaf(a.w, b.y, acc[3][1]);
        }
        __syncthreads();
    }

    // ---- epilogue: bias add + float2 stores ----
    const int col = col0 + tn * 2;
    const float2 bv2 = *reinterpret_cast<const float2*>(&bias[col]);
    #pragma unroll
    for (int r = 0; r < 4; r++) {
        const int row = row0 + tm * 4 + r;
        float2 o;
        o.x = acc[r][0] + bv2.x;
        o.y = acc[r][1] + bv2.y;
        *reinterpret_cast<float2*>(&O[row * Cdim + col]) = o;
    }
}

} // namespace

extern "C" void kernel_launch(void* const* d_in, const int* in_sizes, int n_in,
                              void* d_out, int out_size)
{
    const float* feat = (const float*)d_in[0];
    const float* Wv   = (const float*)d_in[9];
    const float* bv   = (const float*)d_in[10];
    float* out        = (float*)d_out;

    dim3 grid(Cdim / TN, Ndim / TM);   // (8, 16) = 128 blocks
    dim3 block(256);
    vgemm_bias_kernel<<<grid, block>>>(feat, Wv, bv, out);
}